// round 1
// baseline (speedup 1.0000x reference)
#include <cuda_runtime.h>
#include <math.h>

#define E_DIM 512
#define T_DIM 1024
#define B_DIM 8
#define H_DIM 8
#define D_DIM 64
#define WIN   128
#define ROWS  (B_DIM * T_DIM)   // 8192
#define QKV_W (3 * E_DIM)       // 1536

// -------- scratch (static device globals: no runtime allocation) --------
__device__ float g_xn [ROWS * E_DIM];    // 16 MB
__device__ float g_qkv[ROWS * QKV_W];    // 48 MB
__device__ float g_ctx[ROWS * E_DIM];    // 16 MB

// ======================= LayerNorm (per (b,t) row) =======================
__global__ __launch_bounds__(128) void ln_kernel(const float* __restrict__ x,
                                                 const float* __restrict__ gamma,
                                                 const float* __restrict__ beta) {
    const int row = blockIdx.x;
    const int tid = threadIdx.x;
    const float4 v = reinterpret_cast<const float4*>(x + (size_t)row * E_DIM)[tid];
    float s  = v.x + v.y + v.z + v.w;
    float ss = v.x * v.x + v.y * v.y + v.z * v.z + v.w * v.w;
    #pragma unroll
    for (int o = 16; o > 0; o >>= 1) {
        s  += __shfl_down_sync(0xffffffffu, s,  o);
        ss += __shfl_down_sync(0xffffffffu, ss, o);
    }
    __shared__ float sh_s[4], sh_ss[4], sh_mu, sh_rstd;
    const int w = tid >> 5, lane = tid & 31;
    if (lane == 0) { sh_s[w] = s; sh_ss[w] = ss; }
    __syncthreads();
    if (tid == 0) {
        float ts  = sh_s[0] + sh_s[1] + sh_s[2] + sh_s[3];
        float tss = sh_ss[0] + sh_ss[1] + sh_ss[2] + sh_ss[3];
        float mu  = ts * (1.0f / E_DIM);
        float var = tss * (1.0f / E_DIM) - mu * mu;
        sh_mu = mu;
        sh_rstd = rsqrtf(var + 1e-5f);
    }
    __syncthreads();
    const float mu = sh_mu, rstd = sh_rstd;
    const float4 g  = reinterpret_cast<const float4*>(gamma)[tid];
    const float4 be = reinterpret_cast<const float4*>(beta)[tid];
    float4 o;
    o.x = (v.x - mu) * rstd * g.x + be.x;
    o.y = (v.y - mu) * rstd * g.y + be.y;
    o.z = (v.z - mu) * rstd * g.z + be.z;
    o.w = (v.w - mu) * rstd * g.w + be.w;
    reinterpret_cast<float4*>(g_xn + (size_t)row * E_DIM)[tid] = o;
}

// ===================== SGEMM: C[m,n] = bias[n] + sum_k A[m,k]*W[n,k] =====
// A: [M,K] row-major (M = ROWS), W: [N,K] row-major. Tile 128x128x8,
// 256 threads, 8x8 per thread in 2x2 blocks of 4x4 (conflict-free LDS.128).
__global__ __launch_bounds__(256) void sgemm_bias(const float* __restrict__ A,
                                                  const float* __restrict__ Wm,
                                                  const float* __restrict__ bias,
                                                  float* __restrict__ C,
                                                  const int N, const int K) {
    __shared__ float As[8][128];
    __shared__ float Ws[8][128];
    const int bm = blockIdx.y * 128;
    const int bn = blockIdx.x * 128;
    const int tid = threadIdx.x;
    const int tx = tid & 15;        // n sub-tile
    const int ty = tid >> 4;        // m sub-tile
    const int lrow = tid >> 1;      // 0..127
    const int lk   = (tid & 1) << 2; // 0 or 4
    const float* Ap = A  + (size_t)(bm + lrow) * K + lk;
    const float* Wp = Wm + (size_t)(bn + lrow) * K + lk;

    float acc[2][2][4][4];
    #pragma unroll
    for (int a = 0; a < 2; a++)
        #pragma unroll
        for (int b = 0; b < 2; b++)
            #pragma unroll
            for (int i = 0; i < 4; i++)
                #pragma unroll
                for (int j = 0; j < 4; j++) acc[a][b][i][j] = 0.0f;

    for (int k0 = 0; k0 < K; k0 += 8) {
        const float4 av = *reinterpret_cast<const float4*>(Ap + k0);
        const float4 wv = *reinterpret_cast<const float4*>(Wp + k0);
        __syncthreads();   // previous iteration's reads complete
        As[lk + 0][lrow] = av.x; As[lk + 1][lrow] = av.y;
        As[lk + 2][lrow] = av.z; As[lk + 3][lrow] = av.w;
        Ws[lk + 0][lrow] = wv.x; Ws[lk + 1][lrow] = wv.y;
        Ws[lk + 2][lrow] = wv.z; Ws[lk + 3][lrow] = wv.w;
        __syncthreads();
        #pragma unroll
        for (int kk = 0; kk < 8; kk++) {
            const float4 a0 = *reinterpret_cast<const float4*>(&As[kk][ty * 4]);
            const float4 a1 = *reinterpret_cast<const float4*>(&As[kk][ty * 4 + 64]);
            const float4 w0 = *reinterpret_cast<const float4*>(&Ws[kk][tx * 4]);
            const float4 w1 = *reinterpret_cast<const float4*>(&Ws[kk][tx * 4 + 64]);
            const float avr[2][4] = {{a0.x, a0.y, a0.z, a0.w}, {a1.x, a1.y, a1.z, a1.w}};
            const float wvr[2][4] = {{w0.x, w0.y, w0.z, w0.w}, {w1.x, w1.y, w1.z, w1.w}};
            #pragma unroll
            for (int im = 0; im < 2; im++)
                #pragma unroll
                for (int jn = 0; jn < 2; jn++)
                    #pragma unroll
                    for (int i = 0; i < 4; i++)
                        #pragma unroll
                        for (int j = 0; j < 4; j++)
                            acc[im][jn][i][j] = fmaf(avr[im][i], wvr[jn][j], acc[im][jn][i][j]);
        }
    }

    #pragma unroll
    for (int im = 0; im < 2; im++)
        #pragma unroll
        for (int i = 0; i < 4; i++) {
            const int m = bm + im * 64 + ty * 4 + i;
            float* Cp = C + (size_t)m * N;
            #pragma unroll
            for (int jn = 0; jn < 2; jn++) {
                const int n = bn + jn * 64 + tx * 4;
                float4 o;
                o.x = acc[im][jn][i][0] + bias[n + 0];
                o.y = acc[im][jn][i][1] + bias[n + 1];
                o.z = acc[im][jn][i][2] + bias[n + 2];
                o.w = acc[im][jn][i][3] + bias[n + 3];
                *reinterpret_cast<float4*>(Cp + n) = o;
            }
        }
}

// ===================== Windowed causal attention ==========================
// One thread per query. Block = 128 queries of one (b,h). Keys streamed in
// 128-wide chunks through dynamic smem; warp-uniform key loop -> broadcast
// LDS; per-lane window mask via predicated p. No online max (scores are
// O(10) after 1/sqrt(D) scaling; fp32 exp is safe).
#define KV_STRIDE (D_DIM + 4)                         // pad to kill STS conflicts
#define ATTN_SMEM (2 * 128 * KV_STRIDE * 4)           // 69632 B

__global__ __launch_bounds__(128) void attn_kernel(const float* __restrict__ qkv,
                                                   float* __restrict__ ctx) {
    extern __shared__ float smem[];
    float* Ksb = smem;                       // [128][KV_STRIDE]
    float* Vsb = smem + 128 * KV_STRIDE;

    const int qt  = blockIdx.x * 128;
    const int h   = blockIdx.y;
    const int b   = blockIdx.z;
    const int tid = threadIdx.x;
    const int i   = qt + tid;                          // this thread's query
    const int warp = tid >> 5;
    const int wq   = qt + (warp << 5);                 // warp's first query

    const float* qp = qkv + (size_t)(b * T_DIM + i) * QKV_W + h * D_DIM;
    float4 q[16], acc[16];
    #pragma unroll
    for (int d = 0; d < 16; d++) {
        q[d] = reinterpret_cast<const float4*>(qp)[d];
        acc[d] = make_float4(0.f, 0.f, 0.f, 0.f);
    }
    float l = 0.0f;

    for (int cs = qt - WIN; cs < qt + 128; cs += 128) {
        __syncthreads();
        const int j = cs + tid;
        if (j >= 0) {                                    // j < T guaranteed
            const float* kp = qkv + (size_t)(b * T_DIM + j) * QKV_W + E_DIM + h * D_DIM;
            float4* kd = reinterpret_cast<float4*>(Ksb + tid * KV_STRIDE);
            float4* vd = reinterpret_cast<float4*>(Vsb + tid * KV_STRIDE);
            #pragma unroll
            for (int d = 0; d < 16; d++) {
                kd[d] = reinterpret_cast<const float4*>(kp)[d];
                vd[d] = reinterpret_cast<const float4*>(kp + E_DIM)[d];
            }
        }
        __syncthreads();

        int ulo = cs;            if (wq - WIN > ulo) ulo = wq - WIN;  if (ulo < 0) ulo = 0;
        int uhi = cs + 127;      if (wq + 31 < uhi) uhi = wq + 31;

        for (int jj = ulo; jj <= uhi; jj++) {
            const float4* kr = reinterpret_cast<const float4*>(Ksb + (jj - cs) * KV_STRIDE);
            float s0 = 0.f, s1 = 0.f, s2 = 0.f, s3 = 0.f;
            #pragma unroll
            for (int d = 0; d < 16; d += 4) {
                const float4 k0 = kr[d], k1 = kr[d + 1], k2 = kr[d + 2], k3 = kr[d + 3];
                s0 += q[d].x   * k0.x + q[d].y   * k0.y + q[d].z   * k0.z + q[d].w   * k0.w;
                s1 += q[d+1].x * k1.x + q[d+1].y * k1.y + q[d+1].z * k1.z + q[d+1].w * k1.w;
                s2 += q[d+2].x * k2.x + q[d+2].y * k2.y + q[d+2].z * k2.z + q[d+2].w * k2.w;
                s3 += q[d+3].x * k3.x + q[d+3].y * k3.y + q[d+3].z * k3.z + q[d+3].w * k3.w;
            }
            const float s = (s0 + s1) + (s2 + s3);
            const bool ok = (jj <= i) && (jj >= i - WIN);
            const float p = ok ? __expf(s * 0.125f) : 0.0f;   // 1/sqrt(64)
            l += p;
            const float4* vr = reinterpret_cast<const float4*>(Vsb + (jj - cs) * KV_STRIDE);
            #pragma unroll
            for (int d = 0; d < 16; d++) {
                const float4 vv = vr[d];
                acc[d].x = fmaf(p, vv.x, acc[d].x);
                acc[d].y = fmaf(p, vv.y, acc[d].y);
                acc[d].z = fmaf(p, vv.z, acc[d].z);
                acc[d].w = fmaf(p, vv.w, acc[d].w);
            }
        }
    }

    const float rinv = 1.0f / l;                        // l > 0 (j = i always allowed)
    float* op = ctx + (size_t)(b * T_DIM + i) * E_DIM + h * D_DIM;
    #pragma unroll
    for (int d = 0; d < 16; d++) {
        float4 o;
        o.x = acc[d].x * rinv; o.y = acc[d].y * rinv;
        o.z = acc[d].z * rinv; o.w = acc[d].w * rinv;
        reinterpret_cast<float4*>(op)[d] = o;
    }
}

// ============================== launch ====================================
extern "C" void kernel_launch(void* const* d_in, const int* in_sizes, int n_in,
                              void* d_out, int out_size) {
    const float* x     = (const float*)d_in[0];
    // d_in[1] = x_lengths (unused by the reference forward)
    const float* gamma = (const float*)d_in[2];
    const float* beta  = (const float*)d_in[3];
    const float* w_in  = (const float*)d_in[4];
    const float* b_in  = (const float*)d_in[5];
    const float* w_out = (const float*)d_in[6];
    const float* b_out = (const float*)d_in[7];
    float* out = (float*)d_out;

    float *xn, *qkv, *ctx;
    cudaGetSymbolAddress((void**)&xn,  g_xn);
    cudaGetSymbolAddress((void**)&qkv, g_qkv);
    cudaGetSymbolAddress((void**)&ctx, g_ctx);
    cudaFuncSetAttribute(attn_kernel, cudaFuncAttributeMaxDynamicSharedMemorySize, ATTN_SMEM);

    ln_kernel<<<ROWS, 128>>>(x, gamma, beta);
    sgemm_bias<<<dim3(QKV_W / 128, ROWS / 128), 256>>>(xn, w_in, b_in, qkv, QKV_W, E_DIM);
    attn_kernel<<<dim3(T_DIM / 128, H_DIM, B_DIM), 128, ATTN_SMEM>>>(qkv, ctx);
    sgemm_bias<<<dim3(E_DIM / 128, ROWS / 128), 256>>>(ctx, w_out, b_out, out, E_DIM, E_DIM);
}

// round 3
// speedup vs baseline: 1.5747x; 1.5747x over previous
#include <cuda_runtime.h>
#include <cuda_bf16.h>
#include <math.h>
#include <stdint.h>

#define E_DIM 512
#define T_DIM 1024
#define B_DIM 8
#define H_DIM 8
#define D_DIM 64
#define WIN   128
#define ROWS  (B_DIM * T_DIM)   // 8192
#define QKV_W (3 * E_DIM)       // 1536
#define K_DIM 512
#define KC    64                          // K per chunk (64 bf16 = 128B rows)
#define NCHUNK (K_DIM / KC)               // 8
#define TILE_BYTES (128 * 128)            // 128 rows x 128B = 16 KB
#define STAGE_BYTES (4 * TILE_BYTES)      // Ah, Al, Wh, Wl = 64 KB
#define SMEM_GEMM (2 * STAGE_BYTES)       // 128 KB (2 stages)

// -------------------- scratch (__device__ globals) -------------------------
__device__ __nv_bfloat16 g_xn_hi [ROWS * E_DIM];
__device__ __nv_bfloat16 g_xn_lo [ROWS * E_DIM];
__device__ float         g_qkv   [ROWS * QKV_W];
__device__ __nv_bfloat16 g_ctx_hi[ROWS * E_DIM];
__device__ __nv_bfloat16 g_ctx_lo[ROWS * E_DIM];
__device__ __nv_bfloat16 g_win_hi[QKV_W * E_DIM];
__device__ __nv_bfloat16 g_win_lo[QKV_W * E_DIM];
__device__ __nv_bfloat16 g_wout_hi[E_DIM * E_DIM];
__device__ __nv_bfloat16 g_wout_lo[E_DIM * E_DIM];

// ============================ helpers ======================================
__device__ __forceinline__ uint32_t smem_u32(const void* p) {
    uint32_t a;
    asm("{ .reg .u64 t; cvta.to.shared.u64 t, %1; cvt.u32.u64 %0, t; }" : "=r"(a) : "l"(p));
    return a;
}
__device__ __forceinline__ void cp16(uint32_t dst, const void* src) {
    asm volatile("cp.async.cg.shared.global [%0], [%1], 16;" :: "r"(dst), "l"(src));
}
#define CP_COMMIT() asm volatile("cp.async.commit_group;" ::: "memory")
#define CP_WAIT1()  asm volatile("cp.async.wait_group 1;" ::: "memory")
#define CP_WAIT0()  asm volatile("cp.async.wait_group 0;" ::: "memory")

#define LDSM4(R, addr)                                                          \
    asm volatile("ldmatrix.sync.aligned.m8n8.x4.shared.b16 {%0,%1,%2,%3}, [%4];" \
        : "=r"((R)[0]), "=r"((R)[1]), "=r"((R)[2]), "=r"((R)[3]) : "r"(addr))

#define MMA16816(D, A, B0, B1)                                                  \
    asm volatile("mma.sync.aligned.m16n8k16.row.col.f32.bf16.bf16.f32 "         \
        "{%0,%1,%2,%3},{%4,%5,%6,%7},{%8,%9},{%0,%1,%2,%3};"                    \
        : "+f"((D)[0]), "+f"((D)[1]), "+f"((D)[2]), "+f"((D)[3])                \
        : "r"((A)[0]), "r"((A)[1]), "r"((A)[2]), "r"((A)[3]), "r"(B0), "r"(B1))

__device__ __forceinline__ void split_bf16(float x, __nv_bfloat16& h, __nv_bfloat16& l) {
    h = __float2bfloat16(x);
    l = __float2bfloat16(x - __bfloat162float(h));
}

// ======================= LayerNorm -> bf16 hi/lo ===========================
__global__ __launch_bounds__(128) void ln_kernel(const float* __restrict__ x,
                                                 const float* __restrict__ gamma,
                                                 const float* __restrict__ beta) {
    const int row = blockIdx.x;
    const int tid = threadIdx.x;
    const float4 v = reinterpret_cast<const float4*>(x + (size_t)row * E_DIM)[tid];
    float s  = v.x + v.y + v.z + v.w;
    float ss = v.x * v.x + v.y * v.y + v.z * v.z + v.w * v.w;
    #pragma unroll
    for (int o = 16; o > 0; o >>= 1) {
        s  += __shfl_down_sync(0xffffffffu, s,  o);
        ss += __shfl_down_sync(0xffffffffu, ss, o);
    }
    __shared__ float sh_s[4], sh_ss[4], sh_mu, sh_rstd;
    const int w = tid >> 5, lane = tid & 31;
    if (lane == 0) { sh_s[w] = s; sh_ss[w] = ss; }
    __syncthreads();
    if (tid == 0) {
        float ts  = sh_s[0] + sh_s[1] + sh_s[2] + sh_s[3];
        float tss = sh_ss[0] + sh_ss[1] + sh_ss[2] + sh_ss[3];
        float mu  = ts * (1.0f / E_DIM);
        float var = tss * (1.0f / E_DIM) - mu * mu;
        sh_mu = mu; sh_rstd = rsqrtf(var + 1e-5f);
    }
    __syncthreads();
    const float mu = sh_mu, rstd = sh_rstd;
    const float4 g  = reinterpret_cast<const float4*>(gamma)[tid];
    const float4 be = reinterpret_cast<const float4*>(beta)[tid];
    float o[4];
    o[0] = (v.x - mu) * rstd * g.x + be.x;
    o[1] = (v.y - mu) * rstd * g.y + be.y;
    o[2] = (v.z - mu) * rstd * g.z + be.z;
    o[3] = (v.w - mu) * rstd * g.w + be.w;
    __nv_bfloat16 h[4], l[4];
    #pragma unroll
    for (int i = 0; i < 4; i++) split_bf16(o[i], h[i], l[i]);
    __nv_bfloat162* oh = reinterpret_cast<__nv_bfloat162*>(g_xn_hi + (size_t)row * E_DIM);
    __nv_bfloat162* ol = reinterpret_cast<__nv_bfloat162*>(g_xn_lo + (size_t)row * E_DIM);
    oh[2 * tid + 0] = __halves2bfloat162(h[0], h[1]);
    oh[2 * tid + 1] = __halves2bfloat162(h[2], h[3]);
    ol[2 * tid + 0] = __halves2bfloat162(l[0], l[1]);
    ol[2 * tid + 1] = __halves2bfloat162(l[2], l[3]);
}

// ===================== weight fp32 -> bf16 hi/lo (vectorized) ==============
__global__ __launch_bounds__(256) void conv_split(const float* __restrict__ src,
                                                  __nv_bfloat16* __restrict__ hi,
                                                  __nv_bfloat16* __restrict__ lo, int n4) {
    const int i = blockIdx.x * 256 + threadIdx.x;
    if (i < n4) {
        const float4 v = reinterpret_cast<const float4*>(src)[i];
        __nv_bfloat16 h[4], l[4];
        split_bf16(v.x, h[0], l[0]);
        split_bf16(v.y, h[1], l[1]);
        split_bf16(v.z, h[2], l[2]);
        split_bf16(v.w, h[3], l[3]);
        __nv_bfloat162* oh = reinterpret_cast<__nv_bfloat162*>(hi);
        __nv_bfloat162* ol = reinterpret_cast<__nv_bfloat162*>(lo);
        oh[2 * i + 0] = __halves2bfloat162(h[0], h[1]);
        oh[2 * i + 1] = __halves2bfloat162(h[2], h[3]);
        ol[2 * i + 0] = __halves2bfloat162(l[0], l[1]);
        ol[2 * i + 1] = __halves2bfloat162(l[2], l[3]);
    }
}

// ===================== bf16x3 GEMM via mma.sync (HMMA) =====================
// C[m,n] = bias[n] + sum_k A[m,k]*W[n,k]; A [M,K] rm, W [N,K] rm.
// CTA tile 128x128; 8 warps in 2(M) x 4(N); warp tile 64x32.
__global__ __launch_bounds__(256)
void gemm_mma(const __nv_bfloat16* __restrict__ Ah, const __nv_bfloat16* __restrict__ Al,
              const __nv_bfloat16* __restrict__ Wh, const __nv_bfloat16* __restrict__ Wl,
              const float* __restrict__ bias, float* __restrict__ C, const int N) {
    extern __shared__ char smem[];
    const uint32_t sbase = smem_u32(smem);
    const int tid  = threadIdx.x;
    const int wid  = tid >> 5;
    const int lane = tid & 31;
    const int bn = blockIdx.x * 128;
    const int bm = blockIdx.y * 128;

    // ---- gmem -> smem loading pattern (per thread: row tid/2, half (tid&1))
    const int lrow = tid >> 1;
    const int lhalf = (tid & 1);                  // 0 -> bytes 0..63, 1 -> 64..127
    const size_t arow = (size_t)(bm + lrow) * K_DIM + lhalf * 32;  // elem offset
    const size_t wrow = (size_t)(bn + lrow) * K_DIM + lhalf * 32;
    uint32_t st_off[4];
    #pragma unroll
    for (int v = 0; v < 4; v++) {
        uint32_t off = (uint32_t)lrow * 128u + (uint32_t)lhalf * 64u + (uint32_t)v * 16u;
        st_off[v] = off ^ ((off >> 3) & 0x70u);   // SW128 swizzle
    }

    auto load_stage = [&](int s, int c) {
        const uint32_t st = sbase + (uint32_t)s * STAGE_BYTES;
        const int kc = c * KC;
        #pragma unroll
        for (int v = 0; v < 4; v++) {
            cp16(st + st_off[v],                  Ah + arow + kc + v * 8);
            cp16(st + TILE_BYTES + st_off[v],     Al + arow + kc + v * 8);
            cp16(st + 2 * TILE_BYTES + st_off[v], Wh + wrow + kc + v * 8);
            cp16(st + 3 * TILE_BYTES + st_off[v], Wl + wrow + kc + v * 8);
        }
        CP_COMMIT();
    };

    // ---- per-warp ldmatrix addressing (precomputed row offsets + swizzle masks)
    const int wm = (wid & 1) * 64;                // warp M offset
    const int wn = (wid >> 1) * 32;               // warp N offset
    uint32_t a_rowoff[4], a_mask[4];
    #pragma unroll
    for (int mi = 0; mi < 4; mi++) {
        const uint32_t r = (uint32_t)(wm + mi * 16 + (lane & 15));
        a_rowoff[mi] = r * 128u;
        a_mask[mi]   = (a_rowoff[mi] >> 3) & 0x70u;
    }
    const uint32_t a_kb = ((uint32_t)lane >> 4) * 16u;     // lanes 16+: +16B (k+8)
    const int b_lrow = (lane & 7) + ((lane >> 4) << 3);
    uint32_t b_rowoff[2], b_mask[2];
    #pragma unroll
    for (int np = 0; np < 2; np++) {
        const uint32_t r = (uint32_t)(wn + np * 16 + b_lrow);
        b_rowoff[np] = r * 128u;
        b_mask[np]   = (b_rowoff[np] >> 3) & 0x70u;
    }
    const uint32_t b_kb = (((uint32_t)lane >> 3) & 1u) * 16u;

    float acc[4][4][4];
    #pragma unroll
    for (int mi = 0; mi < 4; mi++)
        #pragma unroll
        for (int ni = 0; ni < 4; ni++)
            #pragma unroll
            for (int r = 0; r < 4; r++) acc[mi][ni][r] = 0.0f;

    load_stage(0, 0);
    load_stage(1, 1);

    for (int c = 0; c < NCHUNK; c++) {
        const int s = c & 1;
        const uint32_t st = sbase + (uint32_t)s * STAGE_BYTES;
        if (c + 2 < NCHUNK) CP_WAIT1(); else CP_WAIT0();
        __syncthreads();

        #pragma unroll
        for (int ks = 0; ks < 4; ks++) {
            const uint32_t akb = (uint32_t)ks * 32u + a_kb;
            const uint32_t bkb = (uint32_t)ks * 32u + b_kb;
            uint32_t ah[4][4], al[4][4], bh[2][4], bl[2][4];
            #pragma unroll
            for (int mi = 0; mi < 4; mi++) {
                const uint32_t ao = a_rowoff[mi] + (akb ^ a_mask[mi]);
                LDSM4(ah[mi], st + ao);
                LDSM4(al[mi], st + TILE_BYTES + ao);
            }
            #pragma unroll
            for (int np = 0; np < 2; np++) {
                const uint32_t bo = b_rowoff[np] + (bkb ^ b_mask[np]);
                LDSM4(bh[np], st + 2 * TILE_BYTES + bo);
                LDSM4(bl[np], st + 3 * TILE_BYTES + bo);
            }
            #pragma unroll
            for (int mi = 0; mi < 4; mi++)
                #pragma unroll
                for (int ni = 0; ni < 4; ni++) {
                    const int np = ni >> 1, po = (ni & 1) * 2;
                    MMA16816(acc[mi][ni], ah[mi], bh[np][po], bh[np][po + 1]);
                    MMA16816(acc[mi][ni], ah[mi], bl[np][po], bl[np][po + 1]);
                    MMA16816(acc[mi][ni], al[mi], bh[np][po], bh[np][po + 1]);
                }
        }

        __syncthreads();
        if (c + 2 < NCHUNK) load_stage(s, c + 2);
    }

    // ---- epilogue: direct f32 stores with bias
    const int gid = lane >> 2;
    const int tig = lane & 3;
    float bv[4][2];
    #pragma unroll
    for (int ni = 0; ni < 4; ni++) {
        const int col = bn + wn + ni * 8 + tig * 2;
        bv[ni][0] = bias[col];
        bv[ni][1] = bias[col + 1];
    }
    #pragma unroll
    for (int mi = 0; mi < 4; mi++) {
        const int row0 = bm + wm + mi * 16 + gid;
        float* C0 = C + (size_t)row0 * N;
        float* C1 = C + (size_t)(row0 + 8) * N;
        #pragma unroll
        for (int ni = 0; ni < 4; ni++) {
            const int col = bn + wn + ni * 8 + tig * 2;
            float2 o0, o1;
            o0.x = acc[mi][ni][0] + bv[ni][0];
            o0.y = acc[mi][ni][1] + bv[ni][1];
            o1.x = acc[mi][ni][2] + bv[ni][0];
            o1.y = acc[mi][ni][3] + bv[ni][1];
            *reinterpret_cast<float2*>(C0 + col) = o0;
            *reinterpret_cast<float2*>(C1 + col) = o1;
        }
    }
}

// ===================== Windowed causal attention ==========================
#define KV_STRIDE (D_DIM + 4)
#define ATTN_SMEM (2 * 128 * KV_STRIDE * 4)

__global__ __launch_bounds__(128) void attn_kernel(const float* __restrict__ qkv) {
    extern __shared__ float smemf[];
    float* Ksb = smemf;
    float* Vsb = smemf + 128 * KV_STRIDE;

    const int qt  = blockIdx.x * 128;
    const int h   = blockIdx.y;
    const int b   = blockIdx.z;
    const int tid = threadIdx.x;
    const int i   = qt + tid;
    const int warp = tid >> 5;
    const int wq   = qt + (warp << 5);

    const float* qp = qkv + (size_t)(b * T_DIM + i) * QKV_W + h * D_DIM;
    float4 q[16], acc[16];
    #pragma unroll
    for (int d = 0; d < 16; d++) {
        q[d] = reinterpret_cast<const float4*>(qp)[d];
        acc[d] = make_float4(0.f, 0.f, 0.f, 0.f);
    }
    float l = 0.0f;

    for (int cs = qt - WIN; cs < qt + 128; cs += 128) {
        __syncthreads();
        const int j = cs + tid;
        if (j >= 0) {
            const float* kp = qkv + (size_t)(b * T_DIM + j) * QKV_W + E_DIM + h * D_DIM;
            float4* kd = reinterpret_cast<float4*>(Ksb + tid * KV_STRIDE);
            float4* vd = reinterpret_cast<float4*>(Vsb + tid * KV_STRIDE);
            #pragma unroll
            for (int d = 0; d < 16; d++) {
                kd[d] = reinterpret_cast<const float4*>(kp)[d];
                vd[d] = reinterpret_cast<const float4*>(kp + E_DIM)[d];
            }
        }
        __syncthreads();

        int ulo = cs;       if (wq - WIN > ulo) ulo = wq - WIN;  if (ulo < 0) ulo = 0;
        int uhi = cs + 127; if (wq + 31 < uhi) uhi = wq + 31;

        for (int jj = ulo; jj <= uhi; jj++) {
            const float4* kr = reinterpret_cast<const float4*>(Ksb + (jj - cs) * KV_STRIDE);
            float s0 = 0.f, s1 = 0.f, s2 = 0.f, s3 = 0.f;
            #pragma unroll
            for (int d = 0; d < 16; d += 4) {
                const float4 k0 = kr[d], k1 = kr[d + 1], k2 = kr[d + 2], k3 = kr[d + 3];
                s0 += q[d].x   * k0.x + q[d].y   * k0.y + q[d].z   * k0.z + q[d].w   * k0.w;
                s1 += q[d+1].x * k1.x + q[d+1].y * k1.y + q[d+1].z * k1.z + q[d+1].w * k1.w;
                s2 += q[d+2].x * k2.x + q[d+2].y * k2.y + q[d+2].z * k2.z + q[d+2].w * k2.w;
                s3 += q[d+3].x * k3.x + q[d+3].y * k3.y + q[d+3].z * k3.z + q[d+3].w * k3.w;
            }
            const float s = (s0 + s1) + (s2 + s3);
            const bool ok = (jj <= i) && (jj >= i - WIN);
            const float p = ok ? __expf(s * 0.125f) : 0.0f;
            l += p;
            const float4* vr = reinterpret_cast<const float4*>(Vsb + (jj - cs) * KV_STRIDE);
            #pragma unroll
            for (int d = 0; d < 16; d++) {
                const float4 vv = vr[d];
                acc[d].x = fmaf(p, vv.x, acc[d].x);
                acc[d].y = fmaf(p, vv.y, acc[d].y);
                acc[d].z = fmaf(p, vv.z, acc[d].z);
                acc[d].w = fmaf(p, vv.w, acc[d].w);
            }
        }
    }

    const float rinv = 1.0f / l;
    const size_t obase = (size_t)(b * T_DIM + i) * E_DIM + h * D_DIM;
    __nv_bfloat162* oh = reinterpret_cast<__nv_bfloat162*>(g_ctx_hi + obase);
    __nv_bfloat162* ol = reinterpret_cast<__nv_bfloat162*>(g_ctx_lo + obase);
    #pragma unroll
    for (int d = 0; d < 16; d++) {
        float o[4] = {acc[d].x * rinv, acc[d].y * rinv, acc[d].z * rinv, acc[d].w * rinv};
        __nv_bfloat16 h4[4], l4[4];
        #pragma unroll
        for (int t = 0; t < 4; t++) split_bf16(o[t], h4[t], l4[t]);
        oh[2 * d + 0] = __halves2bfloat162(h4[0], h4[1]);
        oh[2 * d + 1] = __halves2bfloat162(h4[2], h4[3]);
        ol[2 * d + 0] = __halves2bfloat162(l4[0], l4[1]);
        ol[2 * d + 1] = __halves2bfloat162(l4[2], l4[3]);
    }
}

// ============================== launch ====================================
extern "C" void kernel_launch(void* const* d_in, const int* in_sizes, int n_in,
                              void* d_out, int out_size) {
    const float* x     = (const float*)d_in[0];
    const float* gamma = (const float*)d_in[2];
    const float* beta  = (const float*)d_in[3];
    const float* w_in  = (const float*)d_in[4];
    const float* b_in  = (const float*)d_in[5];
    const float* w_out = (const float*)d_in[6];
    const float* b_out = (const float*)d_in[7];
    float* out = (float*)d_out;

    __nv_bfloat16 *xn_hi, *xn_lo, *ctx_hi, *ctx_lo, *win_hi, *win_lo, *wout_hi, *wout_lo;
    float* qkv;
    cudaGetSymbolAddress((void**)&xn_hi,  g_xn_hi);
    cudaGetSymbolAddress((void**)&xn_lo,  g_xn_lo);
    cudaGetSymbolAddress((void**)&qkv,    g_qkv);
    cudaGetSymbolAddress((void**)&ctx_hi, g_ctx_hi);
    cudaGetSymbolAddress((void**)&ctx_lo, g_ctx_lo);
    cudaGetSymbolAddress((void**)&win_hi, g_win_hi);
    cudaGetSymbolAddress((void**)&win_lo, g_win_lo);
    cudaGetSymbolAddress((void**)&wout_hi, g_wout_hi);
    cudaGetSymbolAddress((void**)&wout_lo, g_wout_lo);

    cudaFuncSetAttribute(gemm_mma, cudaFuncAttributeMaxDynamicSharedMemorySize, SMEM_GEMM);
    cudaFuncSetAttribute(attn_kernel, cudaFuncAttributeMaxDynamicSharedMemorySize, ATTN_SMEM);

    ln_kernel<<<ROWS, 128>>>(x, gamma, beta);
    conv_split<<<(QKV_W * E_DIM / 4 + 255) / 256, 256>>>(w_in, win_hi, win_lo, QKV_W * E_DIM / 4);
    conv_split<<<(E_DIM * E_DIM / 4 + 255) / 256, 256>>>(w_out, wout_hi, wout_lo, E_DIM * E_DIM / 4);
    gemm_mma<<<dim3(QKV_W / 128, ROWS / 128), 256, SMEM_GEMM>>>(
        xn_hi, xn_lo, win_hi, win_lo, b_in, qkv, QKV_W);
    attn_kernel<<<dim3(T_DIM / 128, H_DIM, B_DIM), 128, ATTN_SMEM>>>(qkv);
    gemm_mma<<<dim3(E_DIM / 128, ROWS / 128), 256, SMEM_GEMM>>>(
        ctx_hi, ctx_lo, wout_hi, wout_lo, b_out, out, E_DIM);
}

// round 4
// speedup vs baseline: 1.7565x; 1.1155x over previous
#include <cuda_runtime.h>
#include <cuda_bf16.h>
#include <math.h>
#include <stdint.h>

#define E_DIM 512
#define T_DIM 1024
#define B_DIM 8
#define H_DIM 8
#define D_DIM 64
#define WIN   128
#define ROWS  (B_DIM * T_DIM)   // 8192
#define QKV_W (3 * E_DIM)       // 1536
#define K_DIM 512
#define KC    64                          // K per chunk (64 bf16 = 128B rows)
#define NCHUNK (K_DIM / KC)               // 8
#define TILE_BYTES (128 * 128)            // 128 rows x 128B = 16 KB
#define STAGE_BYTES (4 * TILE_BYTES)      // Ah, Al, Wh, Wl = 64 KB
#define NSTAGE 3
#define SMEM_GEMM (NSTAGE * STAGE_BYTES)  // 192 KB

// -------------------- scratch (__device__ globals) -------------------------
__device__ __nv_bfloat16 g_xn_hi [ROWS * E_DIM];
__device__ __nv_bfloat16 g_xn_lo [ROWS * E_DIM];
__device__ float         g_qkv   [ROWS * QKV_W];
__device__ __nv_bfloat16 g_ctx_hi[ROWS * E_DIM];
__device__ __nv_bfloat16 g_ctx_lo[ROWS * E_DIM];
__device__ __nv_bfloat16 g_win_hi[QKV_W * E_DIM];
__device__ __nv_bfloat16 g_win_lo[QKV_W * E_DIM];
__device__ __nv_bfloat16 g_wout_hi[E_DIM * E_DIM];
__device__ __nv_bfloat16 g_wout_lo[E_DIM * E_DIM];

// ============================ helpers ======================================
__device__ __forceinline__ uint32_t smem_u32(const void* p) {
    uint32_t a;
    asm("{ .reg .u64 t; cvta.to.shared.u64 t, %1; cvt.u32.u64 %0, t; }" : "=r"(a) : "l"(p));
    return a;
}
__device__ __forceinline__ void cp16(uint32_t dst, const void* src) {
    asm volatile("cp.async.cg.shared.global [%0], [%1], 16;" :: "r"(dst), "l"(src));
}
#define CP_COMMIT() asm volatile("cp.async.commit_group;" ::: "memory")
#define CP_WAIT2()  asm volatile("cp.async.wait_group 2;" ::: "memory")
#define CP_WAIT1()  asm volatile("cp.async.wait_group 1;" ::: "memory")
#define CP_WAIT0()  asm volatile("cp.async.wait_group 0;" ::: "memory")

#define LDSM4(R, addr)                                                          \
    asm volatile("ldmatrix.sync.aligned.m8n8.x4.shared.b16 {%0,%1,%2,%3}, [%4];" \
        : "=r"((R)[0]), "=r"((R)[1]), "=r"((R)[2]), "=r"((R)[3]) : "r"(addr))

#define MMA16816(D, A, B0, B1)                                                  \
    asm volatile("mma.sync.aligned.m16n8k16.row.col.f32.bf16.bf16.f32 "         \
        "{%0,%1,%2,%3},{%4,%5,%6,%7},{%8,%9},{%0,%1,%2,%3};"                    \
        : "+f"((D)[0]), "+f"((D)[1]), "+f"((D)[2]), "+f"((D)[3])                \
        : "r"((A)[0]), "r"((A)[1]), "r"((A)[2]), "r"((A)[3]), "r"(B0), "r"(B1))

__device__ __forceinline__ void split_bf16(float x, __nv_bfloat16& h, __nv_bfloat16& l) {
    h = __float2bfloat16(x);
    l = __float2bfloat16(x - __bfloat162float(h));
}

// ======================= LayerNorm -> bf16 hi/lo ===========================
__global__ __launch_bounds__(128) void ln_kernel(const float* __restrict__ x,
                                                 const float* __restrict__ gamma,
                                                 const float* __restrict__ beta) {
    const int row = blockIdx.x;
    const int tid = threadIdx.x;
    const float4 v = reinterpret_cast<const float4*>(x + (size_t)row * E_DIM)[tid];
    float s  = v.x + v.y + v.z + v.w;
    float ss = v.x * v.x + v.y * v.y + v.z * v.z + v.w * v.w;
    #pragma unroll
    for (int o = 16; o > 0; o >>= 1) {
        s  += __shfl_down_sync(0xffffffffu, s,  o);
        ss += __shfl_down_sync(0xffffffffu, ss, o);
    }
    __shared__ float sh_s[4], sh_ss[4], sh_mu, sh_rstd;
    const int w = tid >> 5, lane = tid & 31;
    if (lane == 0) { sh_s[w] = s; sh_ss[w] = ss; }
    __syncthreads();
    if (tid == 0) {
        float ts  = sh_s[0] + sh_s[1] + sh_s[2] + sh_s[3];
        float tss = sh_ss[0] + sh_ss[1] + sh_ss[2] + sh_ss[3];
        float mu  = ts * (1.0f / E_DIM);
        float var = tss * (1.0f / E_DIM) - mu * mu;
        sh_mu = mu; sh_rstd = rsqrtf(var + 1e-5f);
    }
    __syncthreads();
    const float mu = sh_mu, rstd = sh_rstd;
    const float4 g  = reinterpret_cast<const float4*>(gamma)[tid];
    const float4 be = reinterpret_cast<const float4*>(beta)[tid];
    float o[4];
    o[0] = (v.x - mu) * rstd * g.x + be.x;
    o[1] = (v.y - mu) * rstd * g.y + be.y;
    o[2] = (v.z - mu) * rstd * g.z + be.z;
    o[3] = (v.w - mu) * rstd * g.w + be.w;
    __nv_bfloat16 h[4], l[4];
    #pragma unroll
    for (int i = 0; i < 4; i++) split_bf16(o[i], h[i], l[i]);
    __nv_bfloat162* oh = reinterpret_cast<__nv_bfloat162*>(g_xn_hi + (size_t)row * E_DIM);
    __nv_bfloat162* ol = reinterpret_cast<__nv_bfloat162*>(g_xn_lo + (size_t)row * E_DIM);
    oh[2 * tid + 0] = __halves2bfloat162(h[0], h[1]);
    oh[2 * tid + 1] = __halves2bfloat162(h[2], h[3]);
    ol[2 * tid + 0] = __halves2bfloat162(l[0], l[1]);
    ol[2 * tid + 1] = __halves2bfloat162(l[2], l[3]);
}

// ===================== weight fp32 -> bf16 hi/lo (vectorized) ==============
__global__ __launch_bounds__(256) void conv_split(const float* __restrict__ src,
                                                  __nv_bfloat16* __restrict__ hi,
                                                  __nv_bfloat16* __restrict__ lo, int n4) {
    const int i = blockIdx.x * 256 + threadIdx.x;
    if (i < n4) {
        const float4 v = reinterpret_cast<const float4*>(src)[i];
        __nv_bfloat16 h[4], l[4];
        split_bf16(v.x, h[0], l[0]);
        split_bf16(v.y, h[1], l[1]);
        split_bf16(v.z, h[2], l[2]);
        split_bf16(v.w, h[3], l[3]);
        __nv_bfloat162* oh = reinterpret_cast<__nv_bfloat162*>(hi);
        __nv_bfloat162* ol = reinterpret_cast<__nv_bfloat162*>(lo);
        oh[2 * i + 0] = __halves2bfloat162(h[0], h[1]);
        oh[2 * i + 1] = __halves2bfloat162(h[2], h[3]);
        ol[2 * i + 0] = __halves2bfloat162(l[0], l[1]);
        ol[2 * i + 1] = __halves2bfloat162(l[2], l[3]);
    }
}

// ===================== bf16x3 GEMM via mma.sync (HMMA) =====================
// C[m,n] = bias[n] + sum_k A[m,k]*W[n,k]; A [M,K] rm, W [N,K] rm.
// CTA tile 128x128; 8 warps 2(M) x 4(N); warp tile 64x32; 3-stage cp.async.
// Split terms issued term-major: 16 independent MMAs between acc reuse.
__global__ __launch_bounds__(256)
void gemm_mma(const __nv_bfloat16* __restrict__ Ah, const __nv_bfloat16* __restrict__ Al,
              const __nv_bfloat16* __restrict__ Wh, const __nv_bfloat16* __restrict__ Wl,
              const float* __restrict__ bias, float* __restrict__ C, const int N) {
    extern __shared__ char smem[];
    const uint32_t sbase = smem_u32(smem);
    const int tid  = threadIdx.x;
    const int wid  = tid >> 5;
    const int lane = tid & 31;
    const int bn = blockIdx.x * 128;
    const int bm = blockIdx.y * 128;

    const int lrow = tid >> 1;
    const int lhalf = (tid & 1);
    const size_t arow = (size_t)(bm + lrow) * K_DIM + lhalf * 32;
    const size_t wrow = (size_t)(bn + lrow) * K_DIM + lhalf * 32;
    uint32_t st_off[4];
    #pragma unroll
    for (int v = 0; v < 4; v++) {
        uint32_t off = (uint32_t)lrow * 128u + (uint32_t)lhalf * 64u + (uint32_t)v * 16u;
        st_off[v] = off ^ ((off >> 3) & 0x70u);
    }

    auto load_stage = [&](int s, int c) {
        const uint32_t st = sbase + (uint32_t)s * STAGE_BYTES;
        const int kc = c * KC;
        #pragma unroll
        for (int v = 0; v < 4; v++) {
            cp16(st + st_off[v],                  Ah + arow + kc + v * 8);
            cp16(st + TILE_BYTES + st_off[v],     Al + arow + kc + v * 8);
            cp16(st + 2 * TILE_BYTES + st_off[v], Wh + wrow + kc + v * 8);
            cp16(st + 3 * TILE_BYTES + st_off[v], Wl + wrow + kc + v * 8);
        }
        CP_COMMIT();
    };

    const int wm = (wid & 1) * 64;
    const int wn = (wid >> 1) * 32;
    uint32_t a_rowoff[4], a_mask[4];
    #pragma unroll
    for (int mi = 0; mi < 4; mi++) {
        const uint32_t r = (uint32_t)(wm + mi * 16 + (lane & 15));
        a_rowoff[mi] = r * 128u;
        a_mask[mi]   = (a_rowoff[mi] >> 3) & 0x70u;
    }
    const uint32_t a_kb = ((uint32_t)lane >> 4) * 16u;
    const int b_lrow = (lane & 7) + ((lane >> 4) << 3);
    uint32_t b_rowoff[2], b_mask[2];
    #pragma unroll
    for (int np = 0; np < 2; np++) {
        const uint32_t r = (uint32_t)(wn + np * 16 + b_lrow);
        b_rowoff[np] = r * 128u;
        b_mask[np]   = (b_rowoff[np] >> 3) & 0x70u;
    }
    const uint32_t b_kb = (((uint32_t)lane >> 3) & 1u) * 16u;

    float acc[4][4][4];
    #pragma unroll
    for (int mi = 0; mi < 4; mi++)
        #pragma unroll
        for (int ni = 0; ni < 4; ni++)
            #pragma unroll
            for (int r = 0; r < 4; r++) acc[mi][ni][r] = 0.0f;

    load_stage(0, 0);
    load_stage(1, 1);
    load_stage(2, 2);

    for (int c = 0; c < NCHUNK; c++) {
        const int s = c % NSTAGE;
        const uint32_t st = sbase + (uint32_t)s * STAGE_BYTES;
        if (c <= NCHUNK - 3)      CP_WAIT2();
        else if (c == NCHUNK - 2) CP_WAIT1();
        else                      CP_WAIT0();
        __syncthreads();

        #pragma unroll
        for (int ks = 0; ks < 4; ks++) {
            const uint32_t akb = (uint32_t)ks * 32u + a_kb;
            const uint32_t bkb = (uint32_t)ks * 32u + b_kb;
            uint32_t ah[4][4], al[4][4], bh[2][4], bl[2][4];
            #pragma unroll
            for (int mi = 0; mi < 4; mi++) {
                const uint32_t ao = a_rowoff[mi] + (akb ^ a_mask[mi]);
                LDSM4(ah[mi], st + ao);
                LDSM4(al[mi], st + TILE_BYTES + ao);
            }
            #pragma unroll
            for (int np = 0; np < 2; np++) {
                const uint32_t bo = b_rowoff[np] + (bkb ^ b_mask[np]);
                LDSM4(bh[np], st + 2 * TILE_BYTES + bo);
                LDSM4(bl[np], st + 3 * TILE_BYTES + bo);
            }
            // term-major: no accumulator is reused within 16 consecutive MMAs
            #pragma unroll
            for (int mi = 0; mi < 4; mi++)
                #pragma unroll
                for (int ni = 0; ni < 4; ni++) {
                    const int np = ni >> 1, po = (ni & 1) * 2;
                    MMA16816(acc[mi][ni], ah[mi], bh[np][po], bh[np][po + 1]);
                }
            #pragma unroll
            for (int mi = 0; mi < 4; mi++)
                #pragma unroll
                for (int ni = 0; ni < 4; ni++) {
                    const int np = ni >> 1, po = (ni & 1) * 2;
                    MMA16816(acc[mi][ni], ah[mi], bl[np][po], bl[np][po + 1]);
                }
            #pragma unroll
            for (int mi = 0; mi < 4; mi++)
                #pragma unroll
                for (int ni = 0; ni < 4; ni++) {
                    const int np = ni >> 1, po = (ni & 1) * 2;
                    MMA16816(acc[mi][ni], al[mi], bh[np][po], bh[np][po + 1]);
                }
        }

        __syncthreads();
        if (c + NSTAGE < NCHUNK) load_stage(s, c + NSTAGE);
    }

    const int gid = lane >> 2;
    const int tig = lane & 3;
    float bv[4][2];
    #pragma unroll
    for (int ni = 0; ni < 4; ni++) {
        const int col = bn + wn + ni * 8 + tig * 2;
        bv[ni][0] = bias[col];
        bv[ni][1] = bias[col + 1];
    }
    #pragma unroll
    for (int mi = 0; mi < 4; mi++) {
        const int row0 = bm + wm + mi * 16 + gid;
        float* C0 = C + (size_t)row0 * N;
        float* C1 = C + (size_t)(row0 + 8) * N;
        #pragma unroll
        for (int ni = 0; ni < 4; ni++) {
            const int col = bn + wn + ni * 8 + tig * 2;
            float2 o0, o1;
            o0.x = acc[mi][ni][0] + bv[ni][0];
            o0.y = acc[mi][ni][1] + bv[ni][1];
            o1.x = acc[mi][ni][2] + bv[ni][0];
            o1.y = acc[mi][ni][3] + bv[ni][1];
            *reinterpret_cast<float2*>(C0 + col) = o0;
            *reinterpret_cast<float2*>(C1 + col) = o1;
        }
    }
}

// ===================== Windowed causal attention ==========================
// 2 threads per query (each owns 32 of 64 dims); 256 threads = 128 queries.
// Half-skew of 36 floats keeps the 2-address LDS broadcast conflict-free.
#define KV_STRIDE 72                            // floats per key row (2x36)
#define ATTN_SMEM (2 * 128 * KV_STRIDE * 4)     // 73728 B

__global__ __launch_bounds__(256) void attn_kernel(const float* __restrict__ qkv) {
    extern __shared__ float smemf[];
    float* Ksb = smemf;
    float* Vsb = smemf + 128 * KV_STRIDE;

    const int qt  = blockIdx.x * 128;
    const int h   = blockIdx.y;
    const int b   = blockIdx.z;
    const int tid = threadIdx.x;
    const int ql  = tid >> 1;                    // local query 0..127
    const int half = tid & 1;                    // which 32-dim half
    const int i   = qt + ql;
    const int warp = tid >> 5;
    const int wq   = qt + (warp << 4);           // warp covers 16 queries

    const float* qp = qkv + (size_t)(b * T_DIM + i) * QKV_W + h * D_DIM + half * 32;
    float4 q[8], acc[8];
    #pragma unroll
    for (int d = 0; d < 8; d++) {
        q[d] = reinterpret_cast<const float4*>(qp)[d];
        acc[d] = make_float4(0.f, 0.f, 0.f, 0.f);
    }
    float l = 0.0f;

    for (int cs = qt - WIN; cs < qt + 128; cs += 128) {
        __syncthreads();
        const int j = cs + ql;
        if (j >= 0) {
            const float* kp = qkv + (size_t)(b * T_DIM + j) * QKV_W + E_DIM + h * D_DIM + half * 32;
            float4* kd = reinterpret_cast<float4*>(Ksb + ql * KV_STRIDE + half * 36);
            float4* vd = reinterpret_cast<float4*>(Vsb + ql * KV_STRIDE + half * 36);
            #pragma unroll
            for (int d = 0; d < 8; d++) {
                kd[d] = reinterpret_cast<const float4*>(kp)[d];
                vd[d] = reinterpret_cast<const float4*>(kp + E_DIM)[d];
            }
        }
        __syncthreads();

        int ulo = cs;       if (wq - WIN > ulo) ulo = wq - WIN;  if (ulo < 0) ulo = 0;
        int uhi = cs + 127; if (wq + 15 < uhi) uhi = wq + 15;

        for (int jj = ulo; jj <= uhi; jj++) {
            const float4* kr = reinterpret_cast<const float4*>(
                Ksb + (jj - cs) * KV_STRIDE + half * 36);
            float s0 = 0.f, s1 = 0.f;
            #pragma unroll
            for (int d = 0; d < 8; d += 2) {
                const float4 k0 = kr[d], k1 = kr[d + 1];
                s0 += q[d].x   * k0.x + q[d].y   * k0.y + q[d].z   * k0.z + q[d].w   * k0.w;
                s1 += q[d+1].x * k1.x + q[d+1].y * k1.y + q[d+1].z * k1.z + q[d+1].w * k1.w;
            }
            const float sp = s0 + s1;
            const float s = sp + __shfl_xor_sync(0xffffffffu, sp, 1);
            const bool ok = (jj <= i) && (jj >= i - WIN);
            const float p = ok ? __expf(s * 0.125f) : 0.0f;
            l += p;
            const float4* vr = reinterpret_cast<const float4*>(
                Vsb + (jj - cs) * KV_STRIDE + half * 36);
            #pragma unroll
            for (int d = 0; d < 8; d++) {
                const float4 vv = vr[d];
                acc[d].x = fmaf(p, vv.x, acc[d].x);
                acc[d].y = fmaf(p, vv.y, acc[d].y);
                acc[d].z = fmaf(p, vv.z, acc[d].z);
                acc[d].w = fmaf(p, vv.w, acc[d].w);
            }
        }
    }

    const float rinv = 1.0f / l;
    const size_t obase = (size_t)(b * T_DIM + i) * E_DIM + h * D_DIM + half * 32;
    __nv_bfloat162* oh = reinterpret_cast<__nv_bfloat162*>(g_ctx_hi + obase);
    __nv_bfloat162* ol = reinterpret_cast<__nv_bfloat162*>(g_ctx_lo + obase);
    #pragma unroll
    for (int d = 0; d < 8; d++) {
        float o[4] = {acc[d].x * rinv, acc[d].y * rinv, acc[d].z * rinv, acc[d].w * rinv};
        __nv_bfloat16 h4[4], l4[4];
        #pragma unroll
        for (int t = 0; t < 4; t++) split_bf16(o[t], h4[t], l4[t]);
        oh[2 * d + 0] = __halves2bfloat162(h4[0], h4[1]);
        oh[2 * d + 1] = __halves2bfloat162(h4[2], h4[3]);
        ol[2 * d + 0] = __halves2bfloat162(l4[0], l4[1]);
        ol[2 * d + 1] = __halves2bfloat162(l4[2], l4[3]);
    }
}

// ============================== launch ====================================
extern "C" void kernel_launch(void* const* d_in, const int* in_sizes, int n_in,
                              void* d_out, int out_size) {
    const float* x     = (const float*)d_in[0];
    const float* gamma = (const float*)d_in[2];
    const float* beta  = (const float*)d_in[3];
    const float* w_in  = (const float*)d_in[4];
    const float* b_in  = (const float*)d_in[5];
    const float* w_out = (const float*)d_in[6];
    const float* b_out = (const float*)d_in[7];
    float* out = (float*)d_out;

    __nv_bfloat16 *xn_hi, *xn_lo, *ctx_hi, *ctx_lo, *win_hi, *win_lo, *wout_hi, *wout_lo;
    float* qkv;
    cudaGetSymbolAddress((void**)&xn_hi,  g_xn_hi);
    cudaGetSymbolAddress((void**)&xn_lo,  g_xn_lo);
    cudaGetSymbolAddress((void**)&qkv,    g_qkv);
    cudaGetSymbolAddress((void**)&ctx_hi, g_ctx_hi);
    cudaGetSymbolAddress((void**)&ctx_lo, g_ctx_lo);
    cudaGetSymbolAddress((void**)&win_hi, g_win_hi);
    cudaGetSymbolAddress((void**)&win_lo, g_win_lo);
    cudaGetSymbolAddress((void**)&wout_hi, g_wout_hi);
    cudaGetSymbolAddress((void**)&wout_lo, g_wout_lo);

    cudaFuncSetAttribute(gemm_mma, cudaFuncAttributeMaxDynamicSharedMemorySize, SMEM_GEMM);
    cudaFuncSetAttribute(attn_kernel, cudaFuncAttributeMaxDynamicSharedMemorySize, ATTN_SMEM);

    ln_kernel<<<ROWS, 128>>>(x, gamma, beta);
    conv_split<<<(QKV_W * E_DIM / 4 + 255) / 256, 256>>>(w_in, win_hi, win_lo, QKV_W * E_DIM / 4);
    conv_split<<<(E_DIM * E_DIM / 4 + 255) / 256, 256>>>(w_out, wout_hi, wout_lo, E_DIM * E_DIM / 4);
    gemm_mma<<<dim3(QKV_W / 128, ROWS / 128), 256, SMEM_GEMM>>>(
        xn_hi, xn_lo, win_hi, win_lo, b_in, qkv, QKV_W);
    attn_kernel<<<dim3(T_DIM / 128, H_DIM, B_DIM), 256, ATTN_SMEM>>>(qkv);
    gemm_mma<<<dim3(E_DIM / 128, ROWS / 128), 256, SMEM_GEMM>>>(
        ctx_hi, ctx_lo, wout_hi, wout_lo, b_out, out, E_DIM);
}